// round 13
// baseline (speedup 1.0000x reference)
#include <cuda_runtime.h>
#include <math.h>
#include <stdint.h>

#define BB 4
#define SS 1024
#define DD 1024
#define HH 16
#define DKK 64
#define DFFV 4096
#define MR (BB*SS)
#define LDQKV 3072
#define LN_EPS 1e-6f

__device__ float g_xn  [MR*DD];
__device__ float g_qkv [MR*LDQKV];
__device__ float g_ctx [MR*DD];
__device__ float g_x1  [MR*DD];
__device__ float g_xn2 [MR*DD];
__device__ float g_ffh [MR*DFFV];
__device__ float g_wqkv[LDQKV*DD];   // [3072][1024] transposed tf32
__device__ float g_wo  [DD*DD];      // [N][K]
__device__ float g_w1t [DFFV*DD];    // [4096][1024]
__device__ float g_w2t [DD*DFFV];    // [1024][4096]
__device__ float g_bqkv[LDQKV];

__device__ __forceinline__ float tf32r(float x) {
    unsigned u;
    asm("cvt.rna.tf32.f32 %0, %1;" : "=r"(u) : "f"(x));
    return __uint_as_float(u);
}
__device__ __forceinline__ void mma_tf32(float* c, const float* a, float b0f, float b1f) {
    asm volatile(
        "mma.sync.aligned.m16n8k8.row.col.f32.tf32.tf32.f32 "
        "{%0,%1,%2,%3}, {%4,%5,%6,%7}, {%8,%9}, {%0,%1,%2,%3};\n"
        : "+f"(c[0]), "+f"(c[1]), "+f"(c[2]), "+f"(c[3])
        : "r"(__float_as_uint(a[0])), "r"(__float_as_uint(a[1])),
          "r"(__float_as_uint(a[2])), "r"(__float_as_uint(a[3])),
          "r"(__float_as_uint(b0f)), "r"(__float_as_uint(b1f)));
}
__device__ __forceinline__ void cpasync16(uint32_t saddr, const void* g) {
    asm volatile("cp.async.cg.shared.global [%0], [%1], 16;\n" :: "r"(saddr), "l"(g));
}
__device__ __forceinline__ void cpasync_commit() {
    asm volatile("cp.async.commit_group;\n" ::: "memory");
}
__device__ __forceinline__ void cpasync_wait0() {
    asm volatile("cp.async.wait_group 0;\n" ::: "memory");
}
__device__ __forceinline__ uint32_t cvta_s(const void* p) {
    return (uint32_t)__cvta_generic_to_shared(p);
}
#define SWZ128(o) ((o) ^ (((o) >> 3) & 0x70))

// -------- weight transpose + tf32 round: out[n][k] = tf32(in[k][n]) --------
__global__ __launch_bounds__(256)
void transpose_tf32(const float* __restrict__ in, float* __restrict__ out, int Kd, int Nd)
{
    __shared__ float tile[32][33];
    int bx = blockIdx.x * 32, by = blockIdx.y * 32;
    int x = threadIdx.x, y = threadIdx.y;
    #pragma unroll
    for (int i = 0; i < 32; i += 8)
        tile[y + i][x] = in[(long)(by + y + i) * Nd + bx + x];
    __syncthreads();
    #pragma unroll
    for (int i = 0; i < 32; i += 8)
        out[(long)(bx + y + i) * Kd + by + x] = tf32r(tile[x][y + i]);
}

__global__ void biascat_kernel(const float* bq, const float* bk, const float* bv, float* o)
{
    int i = blockIdx.x * 256 + threadIdx.x;
    if (i < DD)            o[i] = bq[i];
    else if (i < 2 * DD)   o[i] = bk[i - DD];
    else if (i < 3 * DD)   o[i] = bv[i - 2 * DD];
}

// LayerNorm: torch ddof=1, eps on std; output tf32-rounded
__global__ __launch_bounds__(256)
void layernorm_kernel(const float* __restrict__ x, float* __restrict__ out,
                      const float* __restrict__ alpha, const float* __restrict__ beta)
{
    int row = blockIdx.x;
    float4 v = ((const float4*)(x + (long)row * DD))[threadIdx.x];
    float s  = v.x + v.y + v.z + v.w;
    float sq = v.x*v.x + v.y*v.y + v.z*v.z + v.w*v.w;
    #pragma unroll
    for (int o = 16; o; o >>= 1) {
        s  += __shfl_down_sync(0xffffffffu, s,  o);
        sq += __shfl_down_sync(0xffffffffu, sq, o);
    }
    __shared__ float red[16];
    __shared__ float stats[2];
    int warp = threadIdx.x >> 5, lane = threadIdx.x & 31;
    if (lane == 0) { red[warp] = s; red[warp + 8] = sq; }
    __syncthreads();
    if (threadIdx.x == 0) {
        float ts = 0.f, tq = 0.f;
        #pragma unroll
        for (int i = 0; i < 8; i++) { ts += red[i]; tq += red[i + 8]; }
        float mean = ts / (float)DD;
        float var  = (tq - (float)DD * mean * mean) / (float)(DD - 1);
        var = fmaxf(var, 0.f);
        stats[0] = mean; stats[1] = 1.f / (sqrtf(var) + LN_EPS);
    }
    __syncthreads();
    float mean = stats[0], rstd = stats[1];
    float a = alpha[0], b = beta[0];
    float4 o;
    o.x = tf32r(a * (v.x - mean) * rstd + b);
    o.y = tf32r(a * (v.y - mean) * rstd + b);
    o.z = tf32r(a * (v.z - mean) * rstd + b);
    o.w = tf32r(a * (v.w - mean) * rstd + b);
    ((float4*)(out + (long)row * DD))[threadIdx.x] = o;
}

// ------------- tf32 GEMM: C[M,N] = A[M,K] @ Bt[N,K]^T -----------------------
// CTA 128x128, 4 warps (2x2) of 64x64, BK=32 (one SW128 128B row per chunk),
// 2-stage cp.async double buffer in XOR-swizzled smem.
#define G_STAGE 32768
#define G_DYN (2 * G_STAGE)

template<bool BIAS, bool RELU, bool RES, bool CVT>
__global__ void __launch_bounds__(128, 2)
mma_gemm32(const float* __restrict__ A, const float* __restrict__ Bt,
           const float* __restrict__ bias, const float* __restrict__ res,
           float* __restrict__ C, int K, int N)
{
    extern __shared__ __align__(1024) char smp[];

    int tid = threadIdx.x, warp = tid >> 5, lane = tid & 31;
    int lq = lane >> 2, lr = lane & 3;
    int wm = warp >> 1, wn = warp & 1;
    int rowBase = blockIdx.y << 7, colBase = blockIdx.x << 7;

    int rg = tid >> 3, seg = tid & 7;
    const float* Ag = A  + (long)rowBase * K + seg * 4;
    const float* Bg = Bt + (long)colBase * K + seg * 4;
    uint32_t swo = SWZ128((uint32_t)(rg * 128 + seg * 16));
    uint32_t sb = cvta_s(smp);

    float acc[4][8][4];
    #pragma unroll
    for (int i = 0; i < 4; i++)
        #pragma unroll
        for (int j = 0; j < 8; j++)
            #pragma unroll
            for (int e = 0; e < 4; e++) acc[i][j][e] = 0.f;

    int T = K >> 5;
    #pragma unroll
    for (int g = 0; g < 8; g++) {
        int r = rg + g * 16;
        uint32_t o = swo + g * 2048;
        cpasync16(sb + o,         Ag + (long)r * K);
        cpasync16(sb + 16384 + o, Bg + (long)r * K);
    }
    cpasync_commit();

    uint32_t xorc = (uint32_t)lq << 4;

    for (int t = 0; t < T; t++) {
        cpasync_wait0();
        __syncthreads();
        int buf = t & 1;
        if (t + 1 < T) {
            long k0 = (long)(t + 1) * 32;
            uint32_t ab = sb + (buf ^ 1) * G_STAGE;
            #pragma unroll
            for (int g = 0; g < 8; g++) {
                int r = rg + g * 16;
                uint32_t o = swo + g * 2048;
                cpasync16(ab + o,         Ag + (long)r * K + k0);
                cpasync16(ab + 16384 + o, Bg + (long)r * K + k0);
            }
            cpasync_commit();
        }
        const char* Ab = smp + buf * G_STAGE;
        const char* Bb = Ab + 16384;

        #pragma unroll
        for (int ks = 0; ks < 4; ks++) {
            uint32_t c0 = ((uint32_t)(ks * 8 + lr) * 4) ^ xorc;
            uint32_t c1 = ((uint32_t)(ks * 8 + lr + 4) * 4) ^ xorc;
            float a[4][4];
            #pragma unroll
            for (int mt = 0; mt < 4; mt++) {
                const char* rp = Ab + (wm * 64 + mt * 16 + lq) * 128;
                a[mt][0] = *(const float*)(rp + c0);
                a[mt][1] = *(const float*)(rp + 1024 + c0);
                a[mt][2] = *(const float*)(rp + c1);
                a[mt][3] = *(const float*)(rp + 1024 + c1);
            }
            float b[8][2];
            #pragma unroll
            for (int nt = 0; nt < 8; nt++) {
                const char* np = Bb + (wn * 64 + nt * 8 + lq) * 128;
                b[nt][0] = *(const float*)(np + c0);
                b[nt][1] = *(const float*)(np + c1);
            }
            #pragma unroll
            for (int mt = 0; mt < 4; mt++)
                #pragma unroll
                for (int nt = 0; nt < 8; nt++)
                    mma_tf32(acc[mt][nt], a[mt], b[nt][0], b[nt][1]);
        }
    }

    int erow = rowBase + wm * 64 + lq;
    int ecol = colBase + wn * 64 + lr * 2;
    #pragma unroll
    for (int mt = 0; mt < 4; mt++) {
        #pragma unroll
        for (int nt = 0; nt < 8; nt++) {
            int r = erow + mt * 16;
            int c = ecol + nt * 8;
            float lo0 = acc[mt][nt][0], lo1 = acc[mt][nt][1];
            float hi0 = acc[mt][nt][2], hi1 = acc[mt][nt][3];
            if (BIAS) {
                float2 bv = *(const float2*)(bias + c);
                lo0 += bv.x; lo1 += bv.y; hi0 += bv.x; hi1 += bv.y;
            }
            if (RELU) {
                lo0 = fmaxf(lo0, 0.f); lo1 = fmaxf(lo1, 0.f);
                hi0 = fmaxf(hi0, 0.f); hi1 = fmaxf(hi1, 0.f);
            }
            if (RES) {
                float2 r0 = *(const float2*)(res + (long)r * N + c);
                float2 r1 = *(const float2*)(res + (long)(r + 8) * N + c);
                lo0 += r0.x; lo1 += r0.y; hi0 += r1.x; hi1 += r1.y;
            }
            if (CVT) {
                lo0 = tf32r(lo0); lo1 = tf32r(lo1);
                hi0 = tf32r(hi0); hi1 = tf32r(hi1);
            }
            float2 wlo = {lo0, lo1}, whi = {hi0, hi1};
            *(float2*)(C + (long)r * N + c)       = wlo;
            *(float2*)(C + (long)(r + 8) * N + c) = whi;
        }
    }
}

// ---------------- tensor-core flash attention (qkv fused buffer, LDG/STS) ---
#define KST 68

__global__ __launch_bounds__(256)
void attention_mma(const float* __restrict__ qkv, const int* __restrict__ mask,
                   float* __restrict__ ctx)
{
    __shared__ float Ks[64 * KST];
    __shared__ float Vs[64 * 64];
    __shared__ int   msk[64];

    int tid = threadIdx.x;
    int w = tid >> 5, lane = tid & 31;
    int lq = lane >> 2, lr = lane & 3;
    int bh = blockIdx.y;
    int b = bh >> 4, h = bh & 15;
    int q0 = blockIdx.x * 128;

    const float* qg = qkv + (long)(b * SS + q0 + w * 16) * LDQKV + h * DKK;
    const float* kg = qkv + (long)(b * SS) * LDQKV + DD + h * DKK;
    const float* vg = qkv + (long)(b * SS) * LDQKV + 2 * DD + h * DKK;
    const int* mrow = mask + b * SS;

    float qa[8][4];
    #pragma unroll
    for (int ks = 0; ks < 8; ks++) {
        qa[ks][0] = qg[(long)lq * LDQKV + ks * 8 + lr];
        qa[ks][1] = qg[(long)(lq + 8) * LDQKV + ks * 8 + lr];
        qa[ks][2] = qg[(long)lq * LDQKV + ks * 8 + lr + 4];
        qa[ks][3] = qg[(long)(lq + 8) * LDQKV + ks * 8 + lr + 4];
    }

    float m0 = -INFINITY, m1 = -INFINITY, l0 = 0.f, l1 = 0.f;
    float oacc[8][4];
    #pragma unroll
    for (int nt = 0; nt < 8; nt++)
        #pragma unroll
        for (int e = 0; e < 4; e++) oacc[nt][e] = 0.f;

    for (int kt = 0; kt < 16; kt++) {
        int k0 = kt * 64;
        __syncthreads();
        #pragma unroll
        for (int i = 0; i < 4; i++) {
            int fi = tid + i * 256;
            int kr = fi >> 4;
            int c4 = (fi & 15) << 2;
            float4 tk = *(const float4*)(kg + (long)(k0 + kr) * LDQKV + c4);
            *(float4*)&Ks[kr * KST + c4] = tk;
            float4 tv = *(const float4*)(vg + (long)(k0 + kr) * LDQKV + c4);
            *(float4*)&Vs[kr * 64 + (c4 ^ ((kr & 3) << 3))] = tv;
        }
        if (tid < 16) ((int4*)msk)[tid] = ((const int4*)(mrow + k0))[tid];
        __syncthreads();

        float sacc[8][4];
        #pragma unroll
        for (int nt = 0; nt < 8; nt++)
            #pragma unroll
            for (int e = 0; e < 4; e++) sacc[nt][e] = 0.f;

        #pragma unroll
        for (int nt = 0; nt < 8; nt++) {
            int rb = (nt * 8 + lq) * KST;
            #pragma unroll
            for (int ks = 0; ks < 8; ks++) {
                float b0 = Ks[rb + ks * 8 + lr];
                float b1 = Ks[rb + ks * 8 + lr + 4];
                mma_tf32(sacc[nt], qa[ks], b0, b1);
            }
        }

        float rmax0 = -INFINITY, rmax1 = -INFINITY;
        #pragma unroll
        for (int nt = 0; nt < 8; nt++) {
            int c = nt * 8 + lr * 2;
            int mk0 = msk[c], mk1 = msk[c + 1];
            float s0 = sacc[nt][0] * 0.125f; if (mk0 == 0) s0 = -1e9f;
            float s1 = sacc[nt][1] * 0.125f; if (mk1 == 0) s1 = -1e9f;
            float s2 = sacc[nt][2] * 0.125f; if (mk0 == 0) s2 = -1e9f;
            float s3 = sacc[nt][3] * 0.125f; if (mk1 == 0) s3 = -1e9f;
            sacc[nt][0] = s0; sacc[nt][1] = s1; sacc[nt][2] = s2; sacc[nt][3] = s3;
            rmax0 = fmaxf(rmax0, fmaxf(s0, s1));
            rmax1 = fmaxf(rmax1, fmaxf(s2, s3));
        }
        rmax0 = fmaxf(rmax0, __shfl_xor_sync(0xffffffffu, rmax0, 1));
        rmax0 = fmaxf(rmax0, __shfl_xor_sync(0xffffffffu, rmax0, 2));
        rmax1 = fmaxf(rmax1, __shfl_xor_sync(0xffffffffu, rmax1, 1));
        rmax1 = fmaxf(rmax1, __shfl_xor_sync(0xffffffffu, rmax1, 2));
        float mn0 = fmaxf(m0, rmax0), mn1 = fmaxf(m1, rmax1);
        float corr0 = __expf(m0 - mn0), corr1 = __expf(m1 - mn1);
        float ps0 = 0.f, ps1 = 0.f;
        #pragma unroll
        for (int nt = 0; nt < 8; nt++) {
            float p0 = __expf(sacc[nt][0] - mn0);
            float p1 = __expf(sacc[nt][1] - mn0);
            float p2 = __expf(sacc[nt][2] - mn1);
            float p3 = __expf(sacc[nt][3] - mn1);
            ps0 += p0 + p1; ps1 += p2 + p3;
            sacc[nt][0] = p0; sacc[nt][1] = p1; sacc[nt][2] = p2; sacc[nt][3] = p3;
        }
        ps0 += __shfl_xor_sync(0xffffffffu, ps0, 1);
        ps0 += __shfl_xor_sync(0xffffffffu, ps0, 2);
        ps1 += __shfl_xor_sync(0xffffffffu, ps1, 1);
        ps1 += __shfl_xor_sync(0xffffffffu, ps1, 2);
        l0 = l0 * corr0 + ps0; m0 = mn0;
        l1 = l1 * corr1 + ps1; m1 = mn1;
        #pragma unroll
        for (int nt = 0; nt < 8; nt++) {
            oacc[nt][0] *= corr0; oacc[nt][1] *= corr0;
            oacc[nt][2] *= corr1; oacc[nt][3] *= corr1;
        }

        int base = lane & ~3;
        int src0 = base | (lr >> 1);
        int src1 = src0 | 2;
        int sel = lr & 1;
        #pragma unroll
        for (int ks = 0; ks < 8; ks++) {
            float v0 = __shfl_sync(0xffffffffu, sacc[ks][0], src0);
            float v1 = __shfl_sync(0xffffffffu, sacc[ks][1], src0);
            float v2 = __shfl_sync(0xffffffffu, sacc[ks][2], src0);
            float v3 = __shfl_sync(0xffffffffu, sacc[ks][3], src0);
            float w0 = __shfl_sync(0xffffffffu, sacc[ks][0], src1);
            float w1 = __shfl_sync(0xffffffffu, sacc[ks][1], src1);
            float w2 = __shfl_sync(0xffffffffu, sacc[ks][2], src1);
            float w3 = __shfl_sync(0xffffffffu, sacc[ks][3], src1);
            float pa[4];
            pa[0] = tf32r(sel ? v1 : v0);
            pa[1] = tf32r(sel ? v3 : v2);
            pa[2] = tf32r(sel ? w1 : w0);
            pa[3] = tf32r(sel ? w3 : w2);
            int r0 = (ks * 8 + lr) * 64;
            int r1 = (ks * 8 + lr + 4) * 64;
            int xo = lr << 3;
            #pragma unroll
            for (int nt = 0; nt < 8; nt++) {
                int sw = (nt * 8 + lq) ^ xo;
                float b0 = Vs[r0 + sw];
                float b1 = Vs[r1 + sw];
                mma_tf32(oacc[nt], pa, b0, b1);
            }
        }
    }

    float inv0 = 1.f / l0, inv1 = 1.f / l1;
    long row0 = (long)(b * SS + q0 + w * 16 + lq) * DD + h * DKK;
    long row1 = row0 + 8 * DD;
    #pragma unroll
    for (int nt = 0; nt < 8; nt++) {
        int c = nt * 8 + lr * 2;
        float2 o0, o1;
        o0.x = tf32r(oacc[nt][0] * inv0); o0.y = tf32r(oacc[nt][1] * inv0);
        o1.x = tf32r(oacc[nt][2] * inv1); o1.y = tf32r(oacc[nt][3] * inv1);
        *(float2*)(ctx + row0 + c) = o0;
        *(float2*)(ctx + row1 + c) = o1;
    }
}

extern "C" void kernel_launch(void* const* d_in, const int* in_sizes, int n_in,
                              void* d_out, int out_size)
{
    const float* x    = (const float*)d_in[0];
    const int*   mask = (const int*)  d_in[1];
    const float* wq = (const float*)d_in[2];  const float* bq = (const float*)d_in[3];
    const float* wk = (const float*)d_in[4];  const float* bk = (const float*)d_in[5];
    const float* wv = (const float*)d_in[6];  const float* bv = (const float*)d_in[7];
    const float* wo = (const float*)d_in[8];  const float* bo = (const float*)d_in[9];
    const float* w1 = (const float*)d_in[10]; const float* b1 = (const float*)d_in[11];
    const float* w2 = (const float*)d_in[12]; const float* b2 = (const float*)d_in[13];
    const float* a1 = (const float*)d_in[14]; const float* be1 = (const float*)d_in[15];
    const float* a2 = (const float*)d_in[16]; const float* be2 = (const float*)d_in[17];
    float* out = (float*)d_out;

    float *xn, *qkv, *ctx, *x1, *xn2, *ffh;
    float *wqkvt, *wot, *w1t, *w2t, *bqkv;
    cudaGetSymbolAddress((void**)&xn,    g_xn);
    cudaGetSymbolAddress((void**)&qkv,   g_qkv);
    cudaGetSymbolAddress((void**)&ctx,   g_ctx);
    cudaGetSymbolAddress((void**)&x1,    g_x1);
    cudaGetSymbolAddress((void**)&xn2,   g_xn2);
    cudaGetSymbolAddress((void**)&ffh,   g_ffh);
    cudaGetSymbolAddress((void**)&wqkvt, g_wqkv);
    cudaGetSymbolAddress((void**)&wot,   g_wo);
    cudaGetSymbolAddress((void**)&w1t,   g_w1t);
    cudaGetSymbolAddress((void**)&w2t,   g_w2t);
    cudaGetSymbolAddress((void**)&bqkv,  g_bqkv);

    cudaFuncSetAttribute(mma_gemm32<true,false,false,true >, cudaFuncAttributeMaxDynamicSharedMemorySize, G_DYN);
    cudaFuncSetAttribute(mma_gemm32<true,false,true ,false>, cudaFuncAttributeMaxDynamicSharedMemorySize, G_DYN);
    cudaFuncSetAttribute(mma_gemm32<true,true ,false,true >, cudaFuncAttributeMaxDynamicSharedMemorySize, G_DYN);

    // weight prep: transpose to [N][K] + tf32 round
    transpose_tf32<<<dim3(32, 32),  dim3(32, 8)>>>(wq, wqkvt,               DD, DD);
    transpose_tf32<<<dim3(32, 32),  dim3(32, 8)>>>(wk, wqkvt + DD * DD,     DD, DD);
    transpose_tf32<<<dim3(32, 32),  dim3(32, 8)>>>(wv, wqkvt + 2 * DD * DD, DD, DD);
    transpose_tf32<<<dim3(32, 32),  dim3(32, 8)>>>(wo, wot, DD, DD);
    transpose_tf32<<<dim3(128, 32), dim3(32, 8)>>>(w1, w1t, DD, DFFV);
    transpose_tf32<<<dim3(32, 128), dim3(32, 8)>>>(w2, w2t, DFFV, DD);
    biascat_kernel<<<LDQKV / 256, 256>>>(bq, bk, bv, bqkv);

    dim3 gQKV(LDQKV / 128, MR / 128);  // (24, 32)
    dim3 gD  (DD    / 128, MR / 128);  // (8, 32)
    dim3 gFF (DFFV  / 128, MR / 128);  // (32, 32)

    layernorm_kernel<<<MR, 256>>>(x, xn, a1, be1);
    mma_gemm32<true,false,false,true ><<<gQKV, 128, G_DYN>>>(xn, wqkvt, bqkv, nullptr, qkv, DD, LDQKV);
    attention_mma<<<dim3(SS / 128, BB * HH), 256>>>(qkv, mask, ctx);
    mma_gemm32<true,false,true ,false><<<gD, 128, G_DYN>>>(ctx, wot, bo, x, x1, DD, DD);
    layernorm_kernel<<<MR, 256>>>(x1, xn2, a2, be2);
    mma_gemm32<true,true ,false,true ><<<gFF, 128, G_DYN>>>(xn2, w1t, b1, nullptr, ffh, DD, DFFV);
    mma_gemm32<true,false,true ,false><<<gD, 128, G_DYN>>>(ffh, w2t, b2, x1, out, DFFV, DD);
}

// round 14
// speedup vs baseline: 1.5363x; 1.5363x over previous
#include <cuda_runtime.h>
#include <math.h>
#include <stdint.h>

#define BB 4
#define SS 1024
#define DD 1024
#define HH 16
#define DKK 64
#define DFFV 4096
#define MR (BB*SS)
#define LDQKV 3072
#define LN_EPS 1e-6f

__device__ float g_xn  [MR*DD];
__device__ float g_qkv [MR*LDQKV];
__device__ float g_ctx [MR*DD];
__device__ float g_x1  [MR*DD];
__device__ float g_xn2 [MR*DD];
__device__ float g_ffh [MR*DFFV];
__device__ float g_wqkv[LDQKV*DD];   // [3072][1024] transposed tf32
__device__ float g_wo  [DD*DD];      // [N][K]
__device__ float g_w1t [DFFV*DD];    // [4096][1024]
__device__ float g_w2t [DD*DFFV];    // [1024][4096]
__device__ float g_bqkv[LDQKV];

__device__ __forceinline__ float tf32r(float x) {
    unsigned u;
    asm("cvt.rna.tf32.f32 %0, %1;" : "=r"(u) : "f"(x));
    return __uint_as_float(u);
}
__device__ __forceinline__ void mma_tf32(float* c, const float* a, float b0f, float b1f) {
    asm volatile(
        "mma.sync.aligned.m16n8k8.row.col.f32.tf32.tf32.f32 "
        "{%0,%1,%2,%3}, {%4,%5,%6,%7}, {%8,%9}, {%0,%1,%2,%3};\n"
        : "+f"(c[0]), "+f"(c[1]), "+f"(c[2]), "+f"(c[3])
        : "r"(__float_as_uint(a[0])), "r"(__float_as_uint(a[1])),
          "r"(__float_as_uint(a[2])), "r"(__float_as_uint(a[3])),
          "r"(__float_as_uint(b0f)), "r"(__float_as_uint(b1f)));
}
__device__ __forceinline__ void cpasync16(uint32_t saddr, const void* g) {
    asm volatile("cp.async.cg.shared.global [%0], [%1], 16;\n" :: "r"(saddr), "l"(g));
}
__device__ __forceinline__ void cpasync_commit() {
    asm volatile("cp.async.commit_group;\n" ::: "memory");
}
__device__ __forceinline__ void cpasync_wait0() {
    asm volatile("cp.async.wait_group 0;\n" ::: "memory");
}
__device__ __forceinline__ uint32_t cvta_s(const void* p) {
    return (uint32_t)__cvta_generic_to_shared(p);
}
#define SWZ128(o) ((o) ^ (((o) >> 3) & 0x70))

// -------- fused 4x [DD x DD] weight transpose + tf32 round (z-batched) ------
__global__ __launch_bounds__(256)
void transpose4_tf32(const float* __restrict__ s0, const float* __restrict__ s1,
                     const float* __restrict__ s2, const float* __restrict__ s3,
                     float* __restrict__ d0, float* __restrict__ d1,
                     float* __restrict__ d2, float* __restrict__ d3)
{
    __shared__ float tile[32][33];
    const float* in  = (blockIdx.z == 0) ? s0 : (blockIdx.z == 1) ? s1 : (blockIdx.z == 2) ? s2 : s3;
    float*       out = (blockIdx.z == 0) ? d0 : (blockIdx.z == 1) ? d1 : (blockIdx.z == 2) ? d2 : d3;
    int bx = blockIdx.x * 32, by = blockIdx.y * 32;
    int x = threadIdx.x, y = threadIdx.y;
    #pragma unroll
    for (int i = 0; i < 32; i += 8)
        tile[y + i][x] = in[(long)(by + y + i) * DD + bx + x];
    __syncthreads();
    #pragma unroll
    for (int i = 0; i < 32; i += 8)
        out[(long)(bx + y + i) * DD + by + x] = tf32r(tile[x][y + i]);
}

// -------- generic transpose + tf32 round: out[n][k] = tf32(in[k][n]) --------
__global__ __launch_bounds__(256)
void transpose_tf32(const float* __restrict__ in, float* __restrict__ out, int Kd, int Nd)
{
    __shared__ float tile[32][33];
    int bx = blockIdx.x * 32, by = blockIdx.y * 32;
    int x = threadIdx.x, y = threadIdx.y;
    #pragma unroll
    for (int i = 0; i < 32; i += 8)
        tile[y + i][x] = in[(long)(by + y + i) * Nd + bx + x];
    __syncthreads();
    #pragma unroll
    for (int i = 0; i < 32; i += 8)
        out[(long)(bx + y + i) * Kd + by + x] = tf32r(tile[x][y + i]);
}

__global__ void biascat_kernel(const float* bq, const float* bk, const float* bv, float* o)
{
    int i = blockIdx.x * 256 + threadIdx.x;
    if (i < DD)            o[i] = bq[i];
    else if (i < 2 * DD)   o[i] = bk[i - DD];
    else if (i < 3 * DD)   o[i] = bv[i - 2 * DD];
}

// LayerNorm: torch ddof=1, eps on std; output tf32-rounded
__global__ __launch_bounds__(256)
void layernorm_kernel(const float* __restrict__ x, float* __restrict__ out,
                      const float* __restrict__ alpha, const float* __restrict__ beta)
{
    int row = blockIdx.x;
    float4 v = ((const float4*)(x + (long)row * DD))[threadIdx.x];
    float s  = v.x + v.y + v.z + v.w;
    float sq = v.x*v.x + v.y*v.y + v.z*v.z + v.w*v.w;
    #pragma unroll
    for (int o = 16; o; o >>= 1) {
        s  += __shfl_down_sync(0xffffffffu, s,  o);
        sq += __shfl_down_sync(0xffffffffu, sq, o);
    }
    __shared__ float red[16];
    __shared__ float stats[2];
    int warp = threadIdx.x >> 5, lane = threadIdx.x & 31;
    if (lane == 0) { red[warp] = s; red[warp + 8] = sq; }
    __syncthreads();
    if (threadIdx.x == 0) {
        float ts = 0.f, tq = 0.f;
        #pragma unroll
        for (int i = 0; i < 8; i++) { ts += red[i]; tq += red[i + 8]; }
        float mean = ts / (float)DD;
        float var  = (tq - (float)DD * mean * mean) / (float)(DD - 1);
        var = fmaxf(var, 0.f);
        stats[0] = mean; stats[1] = 1.f / (sqrtf(var) + LN_EPS);
    }
    __syncthreads();
    float mean = stats[0], rstd = stats[1];
    float a = alpha[0], b = beta[0];
    float4 o;
    o.x = tf32r(a * (v.x - mean) * rstd + b);
    o.y = tf32r(a * (v.y - mean) * rstd + b);
    o.z = tf32r(a * (v.z - mean) * rstd + b);
    o.w = tf32r(a * (v.w - mean) * rstd + b);
    ((float4*)(out + (long)row * DD))[threadIdx.x] = o;
}

// ------------- tf32 GEMM: C[M,N] = A[M,K] @ Bt[N,K]^T -----------------------
// CTA 128x128, 4 warps (2x2) of 64x64, BK=32 (one SW128 128B row per chunk),
// 2-stage cp.async double buffer in XOR-swizzled smem.  (R10 proven config)
#define G_STAGE 32768
#define G_DYN (2 * G_STAGE)

template<bool BIAS, bool RELU, bool RES, bool CVT>
__global__ void __launch_bounds__(128, 2)
mma_gemm32(const float* __restrict__ A, const float* __restrict__ Bt,
           const float* __restrict__ bias, const float* __restrict__ res,
           float* __restrict__ C, int K, int N)
{
    extern __shared__ __align__(1024) char smp[];

    int tid = threadIdx.x, warp = tid >> 5, lane = tid & 31;
    int lq = lane >> 2, lr = lane & 3;
    int wm = warp >> 1, wn = warp & 1;
    int rowBase = blockIdx.y << 7, colBase = blockIdx.x << 7;

    int rg = tid >> 3, seg = tid & 7;
    const float* Ag = A  + (long)rowBase * K + seg * 4;
    const float* Bg = Bt + (long)colBase * K + seg * 4;
    uint32_t swo = SWZ128((uint32_t)(rg * 128 + seg * 16));
    uint32_t sb = cvta_s(smp);

    float acc[4][8][4];
    #pragma unroll
    for (int i = 0; i < 4; i++)
        #pragma unroll
        for (int j = 0; j < 8; j++)
            #pragma unroll
            for (int e = 0; e < 4; e++) acc[i][j][e] = 0.f;

    int T = K >> 5;
    #pragma unroll
    for (int g = 0; g < 8; g++) {
        int r = rg + g * 16;
        uint32_t o = swo + g * 2048;
        cpasync16(sb + o,         Ag + (long)r * K);
        cpasync16(sb + 16384 + o, Bg + (long)r * K);
    }
    cpasync_commit();

    uint32_t xorc = (uint32_t)lq << 4;

    for (int t = 0; t < T; t++) {
        cpasync_wait0();
        __syncthreads();
        int buf = t & 1;
        if (t + 1 < T) {
            long k0 = (long)(t + 1) * 32;
            uint32_t ab = sb + (buf ^ 1) * G_STAGE;
            #pragma unroll
            for (int g = 0; g < 8; g++) {
                int r = rg + g * 16;
                uint32_t o = swo + g * 2048;
                cpasync16(ab + o,         Ag + (long)r * K + k0);
                cpasync16(ab + 16384 + o, Bg + (long)r * K + k0);
            }
            cpasync_commit();
        }
        const char* Ab = smp + buf * G_STAGE;
        const char* Bb = Ab + 16384;

        #pragma unroll
        for (int ks = 0; ks < 4; ks++) {
            uint32_t c0 = ((uint32_t)(ks * 8 + lr) * 4) ^ xorc;
            uint32_t c1 = ((uint32_t)(ks * 8 + lr + 4) * 4) ^ xorc;
            float a[4][4];
            #pragma unroll
            for (int mt = 0; mt < 4; mt++) {
                const char* rp = Ab + (wm * 64 + mt * 16 + lq) * 128;
                a[mt][0] = *(const float*)(rp + c0);
                a[mt][1] = *(const float*)(rp + 1024 + c0);
                a[mt][2] = *(const float*)(rp + c1);
                a[mt][3] = *(const float*)(rp + 1024 + c1);
            }
            float b[8][2];
            #pragma unroll
            for (int nt = 0; nt < 8; nt++) {
                const char* np = Bb + (wn * 64 + nt * 8 + lq) * 128;
                b[nt][0] = *(const float*)(np + c0);
                b[nt][1] = *(const float*)(np + c1);
            }
            #pragma unroll
            for (int mt = 0; mt < 4; mt++)
                #pragma unroll
                for (int nt = 0; nt < 8; nt++)
                    mma_tf32(acc[mt][nt], a[mt], b[nt][0], b[nt][1]);
        }
    }

    int erow = rowBase + wm * 64 + lq;
    int ecol = colBase + wn * 64 + lr * 2;
    #pragma unroll
    for (int mt = 0; mt < 4; mt++) {
        #pragma unroll
        for (int nt = 0; nt < 8; nt++) {
            int r = erow + mt * 16;
            int c = ecol + nt * 8;
            float lo0 = acc[mt][nt][0], lo1 = acc[mt][nt][1];
            float hi0 = acc[mt][nt][2], hi1 = acc[mt][nt][3];
            if (BIAS) {
                float2 bv = *(const float2*)(bias + c);
                lo0 += bv.x; lo1 += bv.y; hi0 += bv.x; hi1 += bv.y;
            }
            if (RELU) {
                lo0 = fmaxf(lo0, 0.f); lo1 = fmaxf(lo1, 0.f);
                hi0 = fmaxf(hi0, 0.f); hi1 = fmaxf(hi1, 0.f);
            }
            if (RES) {
                float2 r0 = *(const float2*)(res + (long)r * N + c);
                float2 r1 = *(const float2*)(res + (long)(r + 8) * N + c);
                lo0 += r0.x; lo1 += r0.y; hi0 += r1.x; hi1 += r1.y;
            }
            if (CVT) {
                lo0 = tf32r(lo0); lo1 = tf32r(lo1);
                hi0 = tf32r(hi0); hi1 = tf32r(hi1);
            }
            float2 wlo = {lo0, lo1}, whi = {hi0, hi1};
            *(float2*)(C + (long)r * N + c)       = wlo;
            *(float2*)(C + (long)(r + 8) * N + c) = whi;
        }
    }
}

// ---------------- tensor-core flash attention (qkv fused buffer, LDG/STS) ---
#define KST 68

__global__ __launch_bounds__(256)
void attention_mma(const float* __restrict__ qkv, const int* __restrict__ mask,
                   float* __restrict__ ctx)
{
    __shared__ float Ks[64 * KST];
    __shared__ float Vs[64 * 64];
    __shared__ int   msk[64];

    int tid = threadIdx.x;
    int w = tid >> 5, lane = tid & 31;
    int lq = lane >> 2, lr = lane & 3;
    int bh = blockIdx.y;
    int b = bh >> 4, h = bh & 15;
    int q0 = blockIdx.x * 128;

    const float* qg = qkv + (long)(b * SS + q0 + w * 16) * LDQKV + h * DKK;
    const float* kg = qkv + (long)(b * SS) * LDQKV + DD + h * DKK;
    const float* vg = qkv + (long)(b * SS) * LDQKV + 2 * DD + h * DKK;
    const int* mrow = mask + b * SS;

    float qa[8][4];
    #pragma unroll
    for (int ks = 0; ks < 8; ks++) {
        qa[ks][0] = qg[(long)lq * LDQKV + ks * 8 + lr];
        qa[ks][1] = qg[(long)(lq + 8) * LDQKV + ks * 8 + lr];
        qa[ks][2] = qg[(long)lq * LDQKV + ks * 8 + lr + 4];
        qa[ks][3] = qg[(long)(lq + 8) * LDQKV + ks * 8 + lr + 4];
    }

    float m0 = -INFINITY, m1 = -INFINITY, l0 = 0.f, l1 = 0.f;
    float oacc[8][4];
    #pragma unroll
    for (int nt = 0; nt < 8; nt++)
        #pragma unroll
        for (int e = 0; e < 4; e++) oacc[nt][e] = 0.f;

    for (int kt = 0; kt < 16; kt++) {
        int k0 = kt * 64;
        __syncthreads();
        #pragma unroll
        for (int i = 0; i < 4; i++) {
            int fi = tid + i * 256;
            int kr = fi >> 4;
            int c4 = (fi & 15) << 2;
            float4 tk = *(const float4*)(kg + (long)(k0 + kr) * LDQKV + c4);
            *(float4*)&Ks[kr * KST + c4] = tk;
            float4 tv = *(const float4*)(vg + (long)(k0 + kr) * LDQKV + c4);
            *(float4*)&Vs[kr * 64 + (c4 ^ ((kr & 3) << 3))] = tv;
        }
        if (tid < 16) ((int4*)msk)[tid] = ((const int4*)(mrow + k0))[tid];
        __syncthreads();

        float sacc[8][4];
        #pragma unroll
        for (int nt = 0; nt < 8; nt++)
            #pragma unroll
            for (int e = 0; e < 4; e++) sacc[nt][e] = 0.f;

        #pragma unroll
        for (int nt = 0; nt < 8; nt++) {
            int rb = (nt * 8 + lq) * KST;
            #pragma unroll
            for (int ks = 0; ks < 8; ks++) {
                float b0 = Ks[rb + ks * 8 + lr];
                float b1 = Ks[rb + ks * 8 + lr + 4];
                mma_tf32(sacc[nt], qa[ks], b0, b1);
            }
        }

        float rmax0 = -INFINITY, rmax1 = -INFINITY;
        #pragma unroll
        for (int nt = 0; nt < 8; nt++) {
            int c = nt * 8 + lr * 2;
            int mk0 = msk[c], mk1 = msk[c + 1];
            float s0 = sacc[nt][0] * 0.125f; if (mk0 == 0) s0 = -1e9f;
            float s1 = sacc[nt][1] * 0.125f; if (mk1 == 0) s1 = -1e9f;
            float s2 = sacc[nt][2] * 0.125f; if (mk0 == 0) s2 = -1e9f;
            float s3 = sacc[nt][3] * 0.125f; if (mk1 == 0) s3 = -1e9f;
            sacc[nt][0] = s0; sacc[nt][1] = s1; sacc[nt][2] = s2; sacc[nt][3] = s3;
            rmax0 = fmaxf(rmax0, fmaxf(s0, s1));
            rmax1 = fmaxf(rmax1, fmaxf(s2, s3));
        }
        rmax0 = fmaxf(rmax0, __shfl_xor_sync(0xffffffffu, rmax0, 1));
        rmax0 = fmaxf(rmax0, __shfl_xor_sync(0xffffffffu, rmax0, 2));
        rmax1 = fmaxf(rmax1, __shfl_xor_sync(0xffffffffu, rmax1, 1));
        rmax1 = fmaxf(rmax1, __shfl_xor_sync(0xffffffffu, rmax1, 2));
        float mn0 = fmaxf(m0, rmax0), mn1 = fmaxf(m1, rmax1);
        float corr0 = __expf(m0 - mn0), corr1 = __expf(m1 - mn1);
        float ps0 = 0.f, ps1 = 0.f;
        #pragma unroll
        for (int nt = 0; nt < 8; nt++) {
            float p0 = __expf(sacc[nt][0] - mn0);
            float p1 = __expf(sacc[nt][1] - mn0);
            float p2 = __expf(sacc[nt][2] - mn1);
            float p3 = __expf(sacc[nt][3] - mn1);
            ps0 += p0 + p1; ps1 += p2 + p3;
            sacc[nt][0] = p0; sacc[nt][1] = p1; sacc[nt][2] = p2; sacc[nt][3] = p3;
        }
        ps0 += __shfl_xor_sync(0xffffffffu, ps0, 1);
        ps0 += __shfl_xor_sync(0xffffffffu, ps0, 2);
        ps1 += __shfl_xor_sync(0xffffffffu, ps1, 1);
        ps1 += __shfl_xor_sync(0xffffffffu, ps1, 2);
        l0 = l0 * corr0 + ps0; m0 = mn0;
        l1 = l1 * corr1 + ps1; m1 = mn1;
        #pragma unroll
        for (int nt = 0; nt < 8; nt++) {
            oacc[nt][0] *= corr0; oacc[nt][1] *= corr0;
            oacc[nt][2] *= corr1; oacc[nt][3] *= corr1;
        }

        int base = lane & ~3;
        int src0 = base | (lr >> 1);
        int src1 = src0 | 2;
        int sel = lr & 1;
        #pragma unroll
        for (int ks = 0; ks < 8; ks++) {
            float v0 = __shfl_sync(0xffffffffu, sacc[ks][0], src0);
            float v1 = __shfl_sync(0xffffffffu, sacc[ks][1], src0);
            float v2 = __shfl_sync(0xffffffffu, sacc[ks][2], src0);
            float v3 = __shfl_sync(0xffffffffu, sacc[ks][3], src0);
            float w0 = __shfl_sync(0xffffffffu, sacc[ks][0], src1);
            float w1 = __shfl_sync(0xffffffffu, sacc[ks][1], src1);
            float w2 = __shfl_sync(0xffffffffu, sacc[ks][2], src1);
            float w3 = __shfl_sync(0xffffffffu, sacc[ks][3], src1);
            float pa[4];
            pa[0] = tf32r(sel ? v1 : v0);
            pa[1] = tf32r(sel ? v3 : v2);
            pa[2] = tf32r(sel ? w1 : w0);
            pa[3] = tf32r(sel ? w3 : w2);
            int r0 = (ks * 8 + lr) * 64;
            int r1 = (ks * 8 + lr + 4) * 64;
            int xo = lr << 3;
            #pragma unroll
            for (int nt = 0; nt < 8; nt++) {
                int sw = (nt * 8 + lq) ^ xo;
                float b0 = Vs[r0 + sw];
                float b1 = Vs[r1 + sw];
                mma_tf32(oacc[nt], pa, b0, b1);
            }
        }
    }

    float inv0 = 1.f / l0, inv1 = 1.f / l1;
    long row0 = (long)(b * SS + q0 + w * 16 + lq) * DD + h * DKK;
    long row1 = row0 + 8 * DD;
    #pragma unroll
    for (int nt = 0; nt < 8; nt++) {
        int c = nt * 8 + lr * 2;
        float2 o0, o1;
        o0.x = tf32r(oacc[nt][0] * inv0); o0.y = tf32r(oacc[nt][1] * inv0);
        o1.x = tf32r(oacc[nt][2] * inv1); o1.y = tf32r(oacc[nt][3] * inv1);
        *(float2*)(ctx + row0 + c) = o0;
        *(float2*)(ctx + row1 + c) = o1;
    }
}

extern "C" void kernel_launch(void* const* d_in, const int* in_sizes, int n_in,
                              void* d_out, int out_size)
{
    const float* x    = (const float*)d_in[0];
    const int*   mask = (const int*)  d_in[1];
    const float* wq = (const float*)d_in[2];  const float* bq = (const float*)d_in[3];
    const float* wk = (const float*)d_in[4];  const float* bk = (const float*)d_in[5];
    const float* wv = (const float*)d_in[6];  const float* bv = (const float*)d_in[7];
    const float* wo = (const float*)d_in[8];  const float* bo = (const float*)d_in[9];
    const float* w1 = (const float*)d_in[10]; const float* b1 = (const float*)d_in[11];
    const float* w2 = (const float*)d_in[12]; const float* b2 = (const float*)d_in[13];
    const float* a1 = (const float*)d_in[14]; const float* be1 = (const float*)d_in[15];
    const float* a2 = (const float*)d_in[16]; const float* be2 = (const float*)d_in[17];
    float* out = (float*)d_out;

    float *xn, *qkv, *ctx, *x1, *xn2, *ffh;
    float *wqkvt, *wot, *w1t, *w2t, *bqkv;
    cudaGetSymbolAddress((void**)&xn,    g_xn);
    cudaGetSymbolAddress((void**)&qkv,   g_qkv);
    cudaGetSymbolAddress((void**)&ctx,   g_ctx);
    cudaGetSymbolAddress((void**)&x1,    g_x1);
    cudaGetSymbolAddress((void**)&xn2,   g_xn2);
    cudaGetSymbolAddress((void**)&ffh,   g_ffh);
    cudaGetSymbolAddress((void**)&wqkvt, g_wqkv);
    cudaGetSymbolAddress((void**)&wot,   g_wo);
    cudaGetSymbolAddress((void**)&w1t,   g_w1t);
    cudaGetSymbolAddress((void**)&w2t,   g_w2t);
    cudaGetSymbolAddress((void**)&bqkv,  g_bqkv);

    cudaFuncSetAttribute(mma_gemm32<true,false,false,true >, cudaFuncAttributeMaxDynamicSharedMemorySize, G_DYN);
    cudaFuncSetAttribute(mma_gemm32<true,false,true ,false>, cudaFuncAttributeMaxDynamicSharedMemorySize, G_DYN);
    cudaFuncSetAttribute(mma_gemm32<true,true ,false,true >, cudaFuncAttributeMaxDynamicSharedMemorySize, G_DYN);

    // weight prep: transpose to [N][K] + tf32 round (batched for the 4 DxD)
    transpose4_tf32<<<dim3(32, 32, 4), dim3(32, 8)>>>(
        wq, wk, wv, wo,
        wqkvt, wqkvt + DD * DD, wqkvt + 2 * DD * DD, wot);
    transpose_tf32<<<dim3(128, 32), dim3(32, 8)>>>(w1, w1t, DD, DFFV);
    transpose_tf32<<<dim3(32, 128), dim3(32, 8)>>>(w2, w2t, DFFV, DD);
    biascat_kernel<<<LDQKV / 256, 256>>>(bq, bk, bv, bqkv);

    dim3 gQKV(LDQKV / 128, MR / 128);  // (24, 32)
    dim3 gD  (DD    / 128, MR / 128);  // (8, 32)
    dim3 gFF (DFFV  / 128, MR / 128);  // (32, 32)

    layernorm_kernel<<<MR, 256>>>(x, xn, a1, be1);
    mma_gemm32<true,false,false,true ><<<gQKV, 128, G_DYN>>>(xn, wqkvt, bqkv, nullptr, qkv, DD, LDQKV);
    attention_mma<<<dim3(SS / 128, BB * HH), 256>>>(qkv, mask, ctx);
    mma_gemm32<true,false,true ,false><<<gD, 128, G_DYN>>>(ctx, wot, bo, x, x1, DD, DD);
    layernorm_kernel<<<MR, 256>>>(x1, xn2, a2, be2);
    mma_gemm32<true,true ,false,true ><<<gFF, 128, G_DYN>>>(xn2, w1t, b1, nullptr, ffh, DD, DFFV);
    mma_gemm32<true,false,true ,false><<<gD, 128, G_DYN>>>(ffh, w2t, b2, x1, out, DFFV, DD);
}

// round 15
// speedup vs baseline: 1.5523x; 1.0104x over previous
#include <cuda_runtime.h>
#include <math.h>
#include <stdint.h>

#define BB 4
#define SS 1024
#define DD 1024
#define HH 16
#define DKK 64
#define DFFV 4096
#define MR (BB*SS)
#define LDQKV 3072
#define LN_EPS 1e-6f

__device__ float g_xn  [MR*DD];
__device__ float g_qkv [MR*LDQKV];
__device__ float g_ctx [MR*DD];
__device__ float g_x1  [MR*DD];
__device__ float g_xn2 [MR*DD];
__device__ float g_ffh [MR*DFFV];
__device__ float g_wqkv[LDQKV*DD];   // [3072][1024] transposed tf32
__device__ float g_wo  [DD*DD];      // [N][K]
__device__ float g_w1t [DFFV*DD];    // [4096][1024]
__device__ float g_w2t [DD*DFFV];    // [1024][4096]
__device__ float g_bqkv[LDQKV];

__device__ __forceinline__ float tf32r(float x) {
    unsigned u;
    asm("cvt.rna.tf32.f32 %0, %1;" : "=r"(u) : "f"(x));
    return __uint_as_float(u);
}
__device__ __forceinline__ void mma_tf32(float* c, const float* a, float b0f, float b1f) {
    asm volatile(
        "mma.sync.aligned.m16n8k8.row.col.f32.tf32.tf32.f32 "
        "{%0,%1,%2,%3}, {%4,%5,%6,%7}, {%8,%9}, {%0,%1,%2,%3};\n"
        : "+f"(c[0]), "+f"(c[1]), "+f"(c[2]), "+f"(c[3])
        : "r"(__float_as_uint(a[0])), "r"(__float_as_uint(a[1])),
          "r"(__float_as_uint(a[2])), "r"(__float_as_uint(a[3])),
          "r"(__float_as_uint(b0f)), "r"(__float_as_uint(b1f)));
}
__device__ __forceinline__ void cpasync16(uint32_t saddr, const void* g) {
    asm volatile("cp.async.cg.shared.global [%0], [%1], 16;\n" :: "r"(saddr), "l"(g));
}
__device__ __forceinline__ void cpasync_commit() {
    asm volatile("cp.async.commit_group;\n" ::: "memory");
}
__device__ __forceinline__ void cpasync_wait0() {
    asm volatile("cp.async.wait_group 0;\n" ::: "memory");
}
__device__ __forceinline__ uint32_t cvta_s(const void* p) {
    return (uint32_t)__cvta_generic_to_shared(p);
}
#define SWZ128(o) ((o) ^ (((o) >> 3) & 0x70))

// -------- fused 4x [DD x DD] weight transpose + tf32 round (z-batched) ------
// block (z==0, x==0, y==0) additionally concatenates the QKV biases.
__global__ __launch_bounds__(256)
void transpose4_tf32(const float* __restrict__ s0, const float* __restrict__ s1,
                     const float* __restrict__ s2, const float* __restrict__ s3,
                     float* __restrict__ d0, float* __restrict__ d1,
                     float* __restrict__ d2, float* __restrict__ d3,
                     const float* __restrict__ bq, const float* __restrict__ bk,
                     const float* __restrict__ bv, float* __restrict__ bqkv)
{
    __shared__ float tile[32][33];
    const float* in  = (blockIdx.z == 0) ? s0 : (blockIdx.z == 1) ? s1 : (blockIdx.z == 2) ? s2 : s3;
    float*       out = (blockIdx.z == 0) ? d0 : (blockIdx.z == 1) ? d1 : (blockIdx.z == 2) ? d2 : d3;
    int bx = blockIdx.x * 32, by = blockIdx.y * 32;
    int x = threadIdx.x, y = threadIdx.y;
    int tid = y * 32 + x;
    if (blockIdx.z == 0 && blockIdx.x == 0 && blockIdx.y == 0) {
        #pragma unroll
        for (int i = 0; i < 4; i++) {
            int idx = tid + i * 256;   // 0..1023
            bqkv[idx]            = bq[idx];
            bqkv[idx + DD]       = bk[idx];
            bqkv[idx + 2 * DD]   = bv[idx];
        }
    }
    #pragma unroll
    for (int i = 0; i < 32; i += 8)
        tile[y + i][x] = in[(long)(by + y + i) * DD + bx + x];
    __syncthreads();
    #pragma unroll
    for (int i = 0; i < 32; i += 8)
        out[(long)(bx + y + i) * DD + by + x] = tf32r(tile[x][y + i]);
}

// -------- generic transpose + tf32 round: out[n][k] = tf32(in[k][n]) --------
__global__ __launch_bounds__(256)
void transpose_tf32(const float* __restrict__ in, float* __restrict__ out, int Kd, int Nd)
{
    __shared__ float tile[32][33];
    int bx = blockIdx.x * 32, by = blockIdx.y * 32;
    int x = threadIdx.x, y = threadIdx.y;
    #pragma unroll
    for (int i = 0; i < 32; i += 8)
        tile[y + i][x] = in[(long)(by + y + i) * Nd + bx + x];
    __syncthreads();
    #pragma unroll
    for (int i = 0; i < 32; i += 8)
        out[(long)(bx + y + i) * Kd + by + x] = tf32r(tile[x][y + i]);
}

// LayerNorm: torch ddof=1, eps on std; output tf32-rounded
__global__ __launch_bounds__(256)
void layernorm_kernel(const float* __restrict__ x, float* __restrict__ out,
                      const float* __restrict__ alpha, const float* __restrict__ beta)
{
    int row = blockIdx.x;
    float4 v = ((const float4*)(x + (long)row * DD))[threadIdx.x];
    float s  = v.x + v.y + v.z + v.w;
    float sq = v.x*v.x + v.y*v.y + v.z*v.z + v.w*v.w;
    #pragma unroll
    for (int o = 16; o; o >>= 1) {
        s  += __shfl_down_sync(0xffffffffu, s,  o);
        sq += __shfl_down_sync(0xffffffffu, sq, o);
    }
    __shared__ float red[16];
    __shared__ float stats[2];
    int warp = threadIdx.x >> 5, lane = threadIdx.x & 31;
    if (lane == 0) { red[warp] = s; red[warp + 8] = sq; }
    __syncthreads();
    if (threadIdx.x == 0) {
        float ts = 0.f, tq = 0.f;
        #pragma unroll
        for (int i = 0; i < 8; i++) { ts += red[i]; tq += red[i + 8]; }
        float mean = ts / (float)DD;
        float var  = (tq - (float)DD * mean * mean) / (float)(DD - 1);
        var = fmaxf(var, 0.f);
        stats[0] = mean; stats[1] = 1.f / (sqrtf(var) + LN_EPS);
    }
    __syncthreads();
    float mean = stats[0], rstd = stats[1];
    float a = alpha[0], b = beta[0];
    float4 o;
    o.x = tf32r(a * (v.x - mean) * rstd + b);
    o.y = tf32r(a * (v.y - mean) * rstd + b);
    o.z = tf32r(a * (v.z - mean) * rstd + b);
    o.w = tf32r(a * (v.w - mean) * rstd + b);
    ((float4*)(out + (long)row * DD))[threadIdx.x] = o;
}

// ------------- tf32 GEMM: C[M,N] = A[M,K] @ Bt[N,K]^T -----------------------
// CTA 128x128, 4 warps (2x2) of 64x64, BK=32 (one SW128 128B row per chunk),
// 2-stage cp.async double buffer in XOR-swizzled smem.  (R10 proven config)
#define G_STAGE 32768
#define G_DYN (2 * G_STAGE)

template<bool BIAS, bool RELU, bool RES, bool CVT>
__global__ void __launch_bounds__(128, 2)
mma_gemm32(const float* __restrict__ A, const float* __restrict__ Bt,
           const float* __restrict__ bias, const float* __restrict__ res,
           float* __restrict__ C, int K, int N)
{
    extern __shared__ __align__(1024) char smp[];

    int tid = threadIdx.x, warp = tid >> 5, lane = tid & 31;
    int lq = lane >> 2, lr = lane & 3;
    int wm = warp >> 1, wn = warp & 1;
    int rowBase = blockIdx.y << 7, colBase = blockIdx.x << 7;

    int rg = tid >> 3, seg = tid & 7;
    const float* Ag = A  + (long)rowBase * K + seg * 4;
    const float* Bg = Bt + (long)colBase * K + seg * 4;
    uint32_t swo = SWZ128((uint32_t)(rg * 128 + seg * 16));
    uint32_t sb = cvta_s(smp);

    float acc[4][8][4];
    #pragma unroll
    for (int i = 0; i < 4; i++)
        #pragma unroll
        for (int j = 0; j < 8; j++)
            #pragma unroll
            for (int e = 0; e < 4; e++) acc[i][j][e] = 0.f;

    int T = K >> 5;
    #pragma unroll
    for (int g = 0; g < 8; g++) {
        int r = rg + g * 16;
        uint32_t o = swo + g * 2048;
        cpasync16(sb + o,         Ag + (long)r * K);
        cpasync16(sb + 16384 + o, Bg + (long)r * K);
    }
    cpasync_commit();

    uint32_t xorc = (uint32_t)lq << 4;

    for (int t = 0; t < T; t++) {
        cpasync_wait0();
        __syncthreads();
        int buf = t & 1;
        if (t + 1 < T) {
            long k0 = (long)(t + 1) * 32;
            uint32_t ab = sb + (buf ^ 1) * G_STAGE;
            #pragma unroll
            for (int g = 0; g < 8; g++) {
                int r = rg + g * 16;
                uint32_t o = swo + g * 2048;
                cpasync16(ab + o,         Ag + (long)r * K + k0);
                cpasync16(ab + 16384 + o, Bg + (long)r * K + k0);
            }
            cpasync_commit();
        }
        const char* Ab = smp + buf * G_STAGE;
        const char* Bb = Ab + 16384;

        #pragma unroll
        for (int ks = 0; ks < 4; ks++) {
            uint32_t c0 = ((uint32_t)(ks * 8 + lr) * 4) ^ xorc;
            uint32_t c1 = ((uint32_t)(ks * 8 + lr + 4) * 4) ^ xorc;
            float a[4][4];
            #pragma unroll
            for (int mt = 0; mt < 4; mt++) {
                const char* rp = Ab + (wm * 64 + mt * 16 + lq) * 128;
                a[mt][0] = *(const float*)(rp + c0);
                a[mt][1] = *(const float*)(rp + 1024 + c0);
                a[mt][2] = *(const float*)(rp + c1);
                a[mt][3] = *(const float*)(rp + 1024 + c1);
            }
            float b[8][2];
            #pragma unroll
            for (int nt = 0; nt < 8; nt++) {
                const char* np = Bb + (wn * 64 + nt * 8 + lq) * 128;
                b[nt][0] = *(const float*)(np + c0);
                b[nt][1] = *(const float*)(np + c1);
            }
            #pragma unroll
            for (int mt = 0; mt < 4; mt++)
                #pragma unroll
                for (int nt = 0; nt < 8; nt++)
                    mma_tf32(acc[mt][nt], a[mt], b[nt][0], b[nt][1]);
        }
    }

    int erow = rowBase + wm * 64 + lq;
    int ecol = colBase + wn * 64 + lr * 2;
    #pragma unroll
    for (int mt = 0; mt < 4; mt++) {
        #pragma unroll
        for (int nt = 0; nt < 8; nt++) {
            int r = erow + mt * 16;
            int c = ecol + nt * 8;
            float lo0 = acc[mt][nt][0], lo1 = acc[mt][nt][1];
            float hi0 = acc[mt][nt][2], hi1 = acc[mt][nt][3];
            if (BIAS) {
                float2 bv = *(const float2*)(bias + c);
                lo0 += bv.x; lo1 += bv.y; hi0 += bv.x; hi1 += bv.y;
            }
            if (RELU) {
                lo0 = fmaxf(lo0, 0.f); lo1 = fmaxf(lo1, 0.f);
                hi0 = fmaxf(hi0, 0.f); hi1 = fmaxf(hi1, 0.f);
            }
            if (RES) {
                float2 r0 = *(const float2*)(res + (long)r * N + c);
                float2 r1 = *(const float2*)(res + (long)(r + 8) * N + c);
                lo0 += r0.x; lo1 += r0.y; hi0 += r1.x; hi1 += r1.y;
            }
            if (CVT) {
                lo0 = tf32r(lo0); lo1 = tf32r(lo1);
                hi0 = tf32r(hi0); hi1 = tf32r(hi1);
            }
            float2 wlo = {lo0, lo1}, whi = {hi0, hi1};
            *(float2*)(C + (long)r * N + c)       = wlo;
            *(float2*)(C + (long)(r + 8) * N + c) = whi;
        }
    }
}

// ---------------- tensor-core flash attention ----------------
// q-tile 256 rows per CTA (16 warps / 512 threads), k-tiles of 64.
// Same 34KB static smem; 4 CTAs/SM (2048 thr), grid 256 -> 1 wave.
#define KST 68

__global__ __launch_bounds__(512)
void attention_mma(const float* __restrict__ qkv, const int* __restrict__ mask,
                   float* __restrict__ ctx)
{
    __shared__ float Ks[64 * KST];
    __shared__ float Vs[64 * 64];
    __shared__ int   msk[64];

    int tid = threadIdx.x;
    int w = tid >> 5, lane = tid & 31;
    int lq = lane >> 2, lr = lane & 3;
    int bh = blockIdx.y;
    int b = bh >> 4, h = bh & 15;
    int q0 = blockIdx.x * 256;

    const float* qg = qkv + (long)(b * SS + q0 + w * 16) * LDQKV + h * DKK;
    const float* kg = qkv + (long)(b * SS) * LDQKV + DD + h * DKK;
    const float* vg = qkv + (long)(b * SS) * LDQKV + 2 * DD + h * DKK;
    const int* mrow = mask + b * SS;

    float qa[8][4];
    #pragma unroll
    for (int ks = 0; ks < 8; ks++) {
        qa[ks][0] = qg[(long)lq * LDQKV + ks * 8 + lr];
        qa[ks][1] = qg[(long)(lq + 8) * LDQKV + ks * 8 + lr];
        qa[ks][2] = qg[(long)lq * LDQKV + ks * 8 + lr + 4];
        qa[ks][3] = qg[(long)(lq + 8) * LDQKV + ks * 8 + lr + 4];
    }

    float m0 = -INFINITY, m1 = -INFINITY, l0 = 0.f, l1 = 0.f;
    float oacc[8][4];
    #pragma unroll
    for (int nt = 0; nt < 8; nt++)
        #pragma unroll
        for (int e = 0; e < 4; e++) oacc[nt][e] = 0.f;

    for (int kt = 0; kt < 16; kt++) {
        int k0 = kt * 64;
        __syncthreads();
        #pragma unroll
        for (int i = 0; i < 2; i++) {
            int fi = tid + i * 512;
            int kr = fi >> 4;
            int c4 = (fi & 15) << 2;
            float4 tk = *(const float4*)(kg + (long)(k0 + kr) * LDQKV + c4);
            *(float4*)&Ks[kr * KST + c4] = tk;
            float4 tv = *(const float4*)(vg + (long)(k0 + kr) * LDQKV + c4);
            *(float4*)&Vs[kr * 64 + (c4 ^ ((kr & 3) << 3))] = tv;
        }
        if (tid < 16) ((int4*)msk)[tid] = ((const int4*)(mrow + k0))[tid];
        __syncthreads();

        float sacc[8][4];
        #pragma unroll
        for (int nt = 0; nt < 8; nt++)
            #pragma unroll
            for (int e = 0; e < 4; e++) sacc[nt][e] = 0.f;

        #pragma unroll
        for (int nt = 0; nt < 8; nt++) {
            int rb = (nt * 8 + lq) * KST;
            #pragma unroll
            for (int ks = 0; ks < 8; ks++) {
                float b0 = Ks[rb + ks * 8 + lr];
                float b1 = Ks[rb + ks * 8 + lr + 4];
                mma_tf32(sacc[nt], qa[ks], b0, b1);
            }
        }

        float rmax0 = -INFINITY, rmax1 = -INFINITY;
        #pragma unroll
        for (int nt = 0; nt < 8; nt++) {
            int c = nt * 8 + lr * 2;
            int mk0 = msk[c], mk1 = msk[c + 1];
            float s0 = sacc[nt][0] * 0.125f; if (mk0 == 0) s0 = -1e9f;
            float s1 = sacc[nt][1] * 0.125f; if (mk1 == 0) s1 = -1e9f;
            float s2 = sacc[nt][2] * 0.125f; if (mk0 == 0) s2 = -1e9f;
            float s3 = sacc[nt][3] * 0.125f; if (mk1 == 0) s3 = -1e9f;
            sacc[nt][0] = s0; sacc[nt][1] = s1; sacc[nt][2] = s2; sacc[nt][3] = s3;
            rmax0 = fmaxf(rmax0, fmaxf(s0, s1));
            rmax1 = fmaxf(rmax1, fmaxf(s2, s3));
        }
        rmax0 = fmaxf(rmax0, __shfl_xor_sync(0xffffffffu, rmax0, 1));
        rmax0 = fmaxf(rmax0, __shfl_xor_sync(0xffffffffu, rmax0, 2));
        rmax1 = fmaxf(rmax1, __shfl_xor_sync(0xffffffffu, rmax1, 1));
        rmax1 = fmaxf(rmax1, __shfl_xor_sync(0xffffffffu, rmax1, 2));
        float mn0 = fmaxf(m0, rmax0), mn1 = fmaxf(m1, rmax1);
        float corr0 = __expf(m0 - mn0), corr1 = __expf(m1 - mn1);
        float ps0 = 0.f, ps1 = 0.f;
        #pragma unroll
        for (int nt = 0; nt < 8; nt++) {
            float p0 = __expf(sacc[nt][0] - mn0);
            float p1 = __expf(sacc[nt][1] - mn0);
            float p2 = __expf(sacc[nt][2] - mn1);
            float p3 = __expf(sacc[nt][3] - mn1);
            ps0 += p0 + p1; ps1 += p2 + p3;
            sacc[nt][0] = p0; sacc[nt][1] = p1; sacc[nt][2] = p2; sacc[nt][3] = p3;
        }
        ps0 += __shfl_xor_sync(0xffffffffu, ps0, 1);
        ps0 += __shfl_xor_sync(0xffffffffu, ps0, 2);
        ps1 += __shfl_xor_sync(0xffffffffu, ps1, 1);
        ps1 += __shfl_xor_sync(0xffffffffu, ps1, 2);
        l0 = l0 * corr0 + ps0; m0 = mn0;
        l1 = l1 * corr1 + ps1; m1 = mn1;
        #pragma unroll
        for (int nt = 0; nt < 8; nt++) {
            oacc[nt][0] *= corr0; oacc[nt][1] *= corr0;
            oacc[nt][2] *= corr1; oacc[nt][3] *= corr1;
        }

        int base = lane & ~3;
        int src0 = base | (lr >> 1);
        int src1 = src0 | 2;
        int sel = lr & 1;
        #pragma unroll
        for (int ks = 0; ks < 8; ks++) {
            float v0 = __shfl_sync(0xffffffffu, sacc[ks][0], src0);
            float v1 = __shfl_sync(0xffffffffu, sacc[ks][1], src0);
            float v2 = __shfl_sync(0xffffffffu, sacc[ks][2], src0);
            float v3 = __shfl_sync(0xffffffffu, sacc[ks][3], src0);
            float w0 = __shfl_sync(0xffffffffu, sacc[ks][0], src1);
            float w1 = __shfl_sync(0xffffffffu, sacc[ks][1], src1);
            float w2 = __shfl_sync(0xffffffffu, sacc[ks][2], src1);
            float w3 = __shfl_sync(0xffffffffu, sacc[ks][3], src1);
            float pa[4];
            pa[0] = tf32r(sel ? v1 : v0);
            pa[1] = tf32r(sel ? v3 : v2);
            pa[2] = tf32r(sel ? w1 : w0);
            pa[3] = tf32r(sel ? w3 : w2);
            int r0 = (ks * 8 + lr) * 64;
            int r1 = (ks * 8 + lr + 4) * 64;
            int xo = lr << 3;
            #pragma unroll
            for (int nt = 0; nt < 8; nt++) {
                int sw = (nt * 8 + lq) ^ xo;
                float b0 = Vs[r0 + sw];
                float b1 = Vs[r1 + sw];
                mma_tf32(oacc[nt], pa, b0, b1);
            }
        }
    }

    float inv0 = 1.f / l0, inv1 = 1.f / l1;
    long row0 = (long)(b * SS + q0 + w * 16 + lq) * DD + h * DKK;
    long row1 = row0 + 8 * DD;
    #pragma unroll
    for (int nt = 0; nt < 8; nt++) {
        int c = nt * 8 + lr * 2;
        float2 o0, o1;
        o0.x = tf32r(oacc[nt][0] * inv0); o0.y = tf32r(oacc[nt][1] * inv0);
        o1.x = tf32r(oacc[nt][2] * inv1); o1.y = tf32r(oacc[nt][3] * inv1);
        *(float2*)(ctx + row0 + c) = o0;
        *(float2*)(ctx + row1 + c) = o1;
    }
}

extern "C" void kernel_launch(void* const* d_in, const int* in_sizes, int n_in,
                              void* d_out, int out_size)
{
    const float* x    = (const float*)d_in[0];
    const int*   mask = (const int*)  d_in[1];
    const float* wq = (const float*)d_in[2];  const float* bq = (const float*)d_in[3];
    const float* wk = (const float*)d_in[4];  const float* bk = (const float*)d_in[5];
    const float* wv = (const float*)d_in[6];  const float* bv = (const float*)d_in[7];
    const float* wo = (const float*)d_in[8];  const float* bo = (const float*)d_in[9];
    const float* w1 = (const float*)d_in[10]; const float* b1 = (const float*)d_in[11];
    const float* w2 = (const float*)d_in[12]; const float* b2 = (const float*)d_in[13];
    const float* a1 = (const float*)d_in[14]; const float* be1 = (const float*)d_in[15];
    const float* a2 = (const float*)d_in[16]; const float* be2 = (const float*)d_in[17];
    float* out = (float*)d_out;

    float *xn, *qkv, *ctx, *x1, *xn2, *ffh;
    float *wqkvt, *wot, *w1t, *w2t, *bqkv;
    cudaGetSymbolAddress((void**)&xn,    g_xn);
    cudaGetSymbolAddress((void**)&qkv,   g_qkv);
    cudaGetSymbolAddress((void**)&ctx,   g_ctx);
    cudaGetSymbolAddress((void**)&x1,    g_x1);
    cudaGetSymbolAddress((void**)&xn2,   g_xn2);
    cudaGetSymbolAddress((void**)&ffh,   g_ffh);
    cudaGetSymbolAddress((void**)&wqkvt, g_wqkv);
    cudaGetSymbolAddress((void**)&wot,   g_wo);
    cudaGetSymbolAddress((void**)&w1t,   g_w1t);
    cudaGetSymbolAddress((void**)&w2t,   g_w2t);
    cudaGetSymbolAddress((void**)&bqkv,  g_bqkv);

    cudaFuncSetAttribute(mma_gemm32<true,false,false,true >, cudaFuncAttributeMaxDynamicSharedMemorySize, G_DYN);
    cudaFuncSetAttribute(mma_gemm32<true,false,true ,false>, cudaFuncAttributeMaxDynamicSharedMemorySize, G_DYN);
    cudaFuncSetAttribute(mma_gemm32<true,true ,false,true >, cudaFuncAttributeMaxDynamicSharedMemorySize, G_DYN);

    // weight prep: transpose to [N][K] + tf32 round (batched; bias concat fused)
    transpose4_tf32<<<dim3(32, 32, 4), dim3(32, 8)>>>(
        wq, wk, wv, wo,
        wqkvt, wqkvt + DD * DD, wqkvt + 2 * DD * DD, wot,
        bq, bk, bv, bqkv);
    transpose_tf32<<<dim3(128, 32), dim3(32, 8)>>>(w1, w1t, DD, DFFV);
    transpose_tf32<<<dim3(32, 128), dim3(32, 8)>>>(w2, w2t, DFFV, DD);

    dim3 gQKV(LDQKV / 128, MR / 128);  // (24, 32)
    dim3 gD  (DD    / 128, MR / 128);  // (8, 32)
    dim3 gFF (DFFV  / 128, MR / 128);  // (32, 32)

    layernorm_kernel<<<MR, 256>>>(x, xn, a1, be1);
    mma_gemm32<true,false,false,true ><<<gQKV, 128, G_DYN>>>(xn, wqkvt, bqkv, nullptr, qkv, DD, LDQKV);
    attention_mma<<<dim3(SS / 256, BB * HH), 512>>>(qkv, mask, ctx);
    mma_gemm32<true,false,true ,false><<<gD, 128, G_DYN>>>(ctx, wot, bo, x, x1, DD, DD);
    layernorm_kernel<<<MR, 256>>>(x1, xn2, a2, be2);
    mma_gemm32<true,true ,false,true ><<<gFF, 128, G_DYN>>>(xn2, w1t, b1, nullptr, ffh, DD, DFFV);
    mma_gemm32<true,false,true ,false><<<gD, 128, G_DYN>>>(ffh, w2t, b2, x1, out, DFFV, DD);
}

// round 16
// speedup vs baseline: 2.3676x; 1.5252x over previous
#include <cuda_runtime.h>
#include <cuda_fp16.h>
#include <math.h>
#include <stdint.h>

#define BB 4
#define SS 1024
#define DD 1024
#define HH 16
#define DKK 64
#define DFFV 4096
#define MR (BB*SS)
#define LDQKV 3072
#define LN_EPS 1e-6f

__device__ __half g_xn  [MR*DD];
__device__ __half g_qkv [MR*LDQKV];
__device__ __half g_ctx [MR*DD];
__device__ float  g_x1  [MR*DD];
__device__ __half g_xn2 [MR*DD];
__device__ __half g_ffh [MR*DFFV];
__device__ __half g_wqkv[LDQKV*DD];   // [3072][1024] transposed fp16
__device__ __half g_wo  [DD*DD];      // [N][K]
__device__ __half g_w1t [DFFV*DD];    // [4096][1024]
__device__ __half g_w2t [DD*DFFV];    // [1024][4096]
__device__ float  g_bqkv[LDQKV];

__device__ __forceinline__ void mma_f16(float* c, const unsigned* a, unsigned b0, unsigned b1) {
    asm volatile(
        "mma.sync.aligned.m16n8k16.row.col.f32.f16.f16.f32 "
        "{%0,%1,%2,%3}, {%4,%5,%6,%7}, {%8,%9}, {%0,%1,%2,%3};\n"
        : "+f"(c[0]), "+f"(c[1]), "+f"(c[2]), "+f"(c[3])
        : "r"(a[0]), "r"(a[1]), "r"(a[2]), "r"(a[3]), "r"(b0), "r"(b1));
}
__device__ __forceinline__ void mma_tf32(float* c, const float* a, float b0f, float b1f) {
    asm volatile(
        "mma.sync.aligned.m16n8k8.row.col.f32.tf32.tf32.f32 "
        "{%0,%1,%2,%3}, {%4,%5,%6,%7}, {%8,%9}, {%0,%1,%2,%3};\n"
        : "+f"(c[0]), "+f"(c[1]), "+f"(c[2]), "+f"(c[3])
        : "r"(__float_as_uint(a[0])), "r"(__float_as_uint(a[1])),
          "r"(__float_as_uint(a[2])), "r"(__float_as_uint(a[3])),
          "r"(__float_as_uint(b0f)), "r"(__float_as_uint(b1f)));
}
__device__ __forceinline__ void cpasync16(uint32_t saddr, const void* g) {
    asm volatile("cp.async.cg.shared.global [%0], [%1], 16;\n" :: "r"(saddr), "l"(g));
}
__device__ __forceinline__ void cpasync_commit() {
    asm volatile("cp.async.commit_group;\n" ::: "memory");
}
__device__ __forceinline__ void cpasync_wait0() {
    asm volatile("cp.async.wait_group 0;\n" ::: "memory");
}
__device__ __forceinline__ uint32_t cvta_s(const void* p) {
    return (uint32_t)__cvta_generic_to_shared(p);
}
#define SWZ128(o) ((o) ^ (((o) >> 3) & 0x70))

// -------- fused 4x [DD x DD] weight transpose + fp16 round (z-batched) ------
__global__ __launch_bounds__(256)
void transpose4_f16(const float* __restrict__ s0, const float* __restrict__ s1,
                    const float* __restrict__ s2, const float* __restrict__ s3,
                    __half* __restrict__ d0, __half* __restrict__ d1,
                    __half* __restrict__ d2, __half* __restrict__ d3,
                    const float* __restrict__ bq, const float* __restrict__ bk,
                    const float* __restrict__ bv, float* __restrict__ bqkv)
{
    __shared__ float tile[32][33];
    const float* in = (blockIdx.z == 0) ? s0 : (blockIdx.z == 1) ? s1 : (blockIdx.z == 2) ? s2 : s3;
    __half*     out = (blockIdx.z == 0) ? d0 : (blockIdx.z == 1) ? d1 : (blockIdx.z == 2) ? d2 : d3;
    int bx = blockIdx.x * 32, by = blockIdx.y * 32;
    int x = threadIdx.x, y = threadIdx.y;
    int tid = y * 32 + x;
    if (blockIdx.z == 0 && blockIdx.x == 0 && blockIdx.y == 0) {
        #pragma unroll
        for (int i = 0; i < 4; i++) {
            int idx = tid + i * 256;
            bqkv[idx]          = bq[idx];
            bqkv[idx + DD]     = bk[idx];
            bqkv[idx + 2 * DD] = bv[idx];
        }
    }
    #pragma unroll
    for (int i = 0; i < 32; i += 8)
        tile[y + i][x] = in[(long)(by + y + i) * DD + bx + x];
    __syncthreads();
    #pragma unroll
    for (int i = 0; i < 32; i += 8)
        out[(long)(bx + y + i) * DD + by + x] = __float2half_rn(tile[x][y + i]);
}

__global__ __launch_bounds__(256)
void transpose_f16(const float* __restrict__ in, __half* __restrict__ out, int Kd, int Nd)
{
    __shared__ float tile[32][33];
    int bx = blockIdx.x * 32, by = blockIdx.y * 32;
    int x = threadIdx.x, y = threadIdx.y;
    #pragma unroll
    for (int i = 0; i < 32; i += 8)
        tile[y + i][x] = in[(long)(by + y + i) * Nd + bx + x];
    __syncthreads();
    #pragma unroll
    for (int i = 0; i < 32; i += 8)
        out[(long)(bx + y + i) * Kd + by + x] = __float2half_rn(tile[x][y + i]);
}

// LayerNorm: torch ddof=1, eps on std; output fp16
__global__ __launch_bounds__(256)
void layernorm_kernel(const float* __restrict__ x, __half* __restrict__ out,
                      const float* __restrict__ alpha, const float* __restrict__ beta)
{
    int row = blockIdx.x;
    float4 v = ((const float4*)(x + (long)row * DD))[threadIdx.x];
    float s  = v.x + v.y + v.z + v.w;
    float sq = v.x*v.x + v.y*v.y + v.z*v.z + v.w*v.w;
    #pragma unroll
    for (int o = 16; o; o >>= 1) {
        s  += __shfl_down_sync(0xffffffffu, s,  o);
        sq += __shfl_down_sync(0xffffffffu, sq, o);
    }
    __shared__ float red[16];
    __shared__ float stats[2];
    int warp = threadIdx.x >> 5, lane = threadIdx.x & 31;
    if (lane == 0) { red[warp] = s; red[warp + 8] = sq; }
    __syncthreads();
    if (threadIdx.x == 0) {
        float ts = 0.f, tq = 0.f;
        #pragma unroll
        for (int i = 0; i < 8; i++) { ts += red[i]; tq += red[i + 8]; }
        float mean = ts / (float)DD;
        float var  = (tq - (float)DD * mean * mean) / (float)(DD - 1);
        var = fmaxf(var, 0.f);
        stats[0] = mean; stats[1] = 1.f / (sqrtf(var) + LN_EPS);
    }
    __syncthreads();
    float mean = stats[0], rstd = stats[1];
    float a = alpha[0], b = beta[0];
    __half2 h0 = __floats2half2_rn(a * (v.x - mean) * rstd + b,
                                   a * (v.y - mean) * rstd + b);
    __half2 h1 = __floats2half2_rn(a * (v.z - mean) * rstd + b,
                                   a * (v.w - mean) * rstd + b);
    uint2 pk;
    pk.x = *(unsigned*)&h0; pk.y = *(unsigned*)&h1;
    ((uint2*)(out + (long)row * DD))[threadIdx.x] = pk;
}

// ------------- fp16 GEMM: C[M,N] = A[M,K] @ Bt[N,K]^T -----------------------
// CTA 128x128, 4 warps (2x2) of 64x64, BK=64 halfs (one 128B SW128 row),
// 2-stage cp.async double buffer in XOR-swizzled smem.
#define G_STAGE 32768
#define G_DYN (2 * G_STAGE)

template<bool BIAS, bool RELU, bool RES, bool HOUT>
__global__ void __launch_bounds__(128, 2)
mma_gemm16(const __half* __restrict__ A, const __half* __restrict__ Bt,
           const float* __restrict__ bias, const float* __restrict__ res,
           void* __restrict__ Cv, int K, int N)
{
    extern __shared__ __align__(1024) char smp[];

    int tid = threadIdx.x, warp = tid >> 5, lane = tid & 31;
    int lq = lane >> 2, lr = lane & 3;
    int wm = warp >> 1, wn = warp & 1;
    int rowBase = blockIdx.y << 7, colBase = blockIdx.x << 7;

    int rg = tid >> 3, seg = tid & 7;
    const __half* Ag = A  + (long)(rowBase) * K + seg * 8;
    const __half* Bg = Bt + (long)(colBase) * K + seg * 8;
    uint32_t swo = SWZ128((uint32_t)(rg * 128 + seg * 16));
    uint32_t sb = cvta_s(smp);

    float acc[4][8][4];
    #pragma unroll
    for (int i = 0; i < 4; i++)
        #pragma unroll
        for (int j = 0; j < 8; j++)
            #pragma unroll
            for (int e = 0; e < 4; e++) acc[i][j][e] = 0.f;

    int T = K >> 6;
    #pragma unroll
    for (int g = 0; g < 8; g++) {
        int r = rg + g * 16;
        uint32_t o = swo + g * 2048;
        cpasync16(sb + o,         Ag + (long)r * K);
        cpasync16(sb + 16384 + o, Bg + (long)r * K);
    }
    cpasync_commit();

    uint32_t xorc = (uint32_t)lq << 4;

    for (int t = 0; t < T; t++) {
        cpasync_wait0();
        __syncthreads();
        int buf = t & 1;
        if (t + 1 < T) {
            long k0 = (long)(t + 1) * 64;
            uint32_t ab = sb + (buf ^ 1) * G_STAGE;
            #pragma unroll
            for (int g = 0; g < 8; g++) {
                int r = rg + g * 16;
                uint32_t o = swo + g * 2048;
                cpasync16(ab + o,         Ag + (long)r * K + k0);
                cpasync16(ab + 16384 + o, Bg + (long)r * K + k0);
            }
            cpasync_commit();
        }
        const char* Ab = smp + buf * G_STAGE;
        const char* Bb = Ab + 16384;

        #pragma unroll
        for (int ks = 0; ks < 4; ks++) {
            uint32_t c0 = ((uint32_t)(32 * ks + 4 * lr)) ^ xorc;
            uint32_t c1 = c0 ^ 16u;
            unsigned a[4][4];
            #pragma unroll
            for (int mt = 0; mt < 4; mt++) {
                const char* rp = Ab + (wm * 64 + mt * 16 + lq) * 128;
                a[mt][0] = *(const unsigned*)(rp + c0);
                a[mt][1] = *(const unsigned*)(rp + 1024 + c0);
                a[mt][2] = *(const unsigned*)(rp + c1);
                a[mt][3] = *(const unsigned*)(rp + 1024 + c1);
            }
            unsigned b[8][2];
            #pragma unroll
            for (int nt = 0; nt < 8; nt++) {
                const char* np = Bb + (wn * 64 + nt * 8 + lq) * 128;
                b[nt][0] = *(const unsigned*)(np + c0);
                b[nt][1] = *(const unsigned*)(np + c1);
            }
            #pragma unroll
            for (int mt = 0; mt < 4; mt++)
                #pragma unroll
                for (int nt = 0; nt < 8; nt++)
                    mma_f16(acc[mt][nt], a[mt], b[nt][0], b[nt][1]);
        }
    }

    int erow = rowBase + wm * 64 + lq;
    int ecol = colBase + wn * 64 + lr * 2;
    #pragma unroll
    for (int mt = 0; mt < 4; mt++) {
        #pragma unroll
        for (int nt = 0; nt < 8; nt++) {
            int r = erow + mt * 16;
            int c = ecol + nt * 8;
            float lo0 = acc[mt][nt][0], lo1 = acc[mt][nt][1];
            float hi0 = acc[mt][nt][2], hi1 = acc[mt][nt][3];
            if (BIAS) {
                float2 bv = *(const float2*)(bias + c);
                lo0 += bv.x; lo1 += bv.y; hi0 += bv.x; hi1 += bv.y;
            }
            if (RELU) {
                lo0 = fmaxf(lo0, 0.f); lo1 = fmaxf(lo1, 0.f);
                hi0 = fmaxf(hi0, 0.f); hi1 = fmaxf(hi1, 0.f);
            }
            if (RES) {
                float2 r0 = *(const float2*)(res + (long)r * N + c);
                float2 r1 = *(const float2*)(res + (long)(r + 8) * N + c);
                lo0 += r0.x; lo1 += r0.y; hi0 += r1.x; hi1 += r1.y;
            }
            if (HOUT) {
                __half* C = (__half*)Cv;
                *(__half2*)(C + (long)r * N + c)       = __floats2half2_rn(lo0, lo1);
                *(__half2*)(C + (long)(r + 8) * N + c) = __floats2half2_rn(hi0, hi1);
            } else {
                float* C = (float*)Cv;
                float2 wlo = {lo0, lo1}, whi = {hi0, hi1};
                *(float2*)(C + (long)r * N + c)       = wlo;
                *(float2*)(C + (long)(r + 8) * N + c) = whi;
            }
        }
    }
}

// ---------------- tensor-core flash attention (tf32 core, fp16 inputs) ------
// q-tile 256 rows per CTA (16 warps / 512 threads), k-tiles of 64.
#define KST 68

__global__ __launch_bounds__(512)
void attention_mma(const __half* __restrict__ qkv, const int* __restrict__ mask,
                   __half* __restrict__ ctx)
{
    __shared__ float Ks[64 * KST];
    __shared__ float Vs[64 * 64];
    __shared__ int   msk[64];

    int tid = threadIdx.x;
    int w = tid >> 5, lane = tid & 31;
    int lq = lane >> 2, lr = lane & 3;
    int bh = blockIdx.y;
    int b = bh >> 4, h = bh & 15;
    int q0 = blockIdx.x * 256;

    const __half* qg = qkv + (long)(b * SS + q0 + w * 16) * LDQKV + h * DKK;
    const __half* kg = qkv + (long)(b * SS) * LDQKV + DD + h * DKK;
    const __half* vg = qkv + (long)(b * SS) * LDQKV + 2 * DD + h * DKK;
    const int* mrow = mask + b * SS;

    // q fragments (fp16 exactly representable in tf32 -> plain convert)
    float qa[8][4];
    #pragma unroll
    for (int ks = 0; ks < 8; ks++) {
        qa[ks][0] = __half2float(qg[(long)lq * LDQKV + ks * 8 + lr]);
        qa[ks][1] = __half2float(qg[(long)(lq + 8) * LDQKV + ks * 8 + lr]);
        qa[ks][2] = __half2float(qg[(long)lq * LDQKV + ks * 8 + lr + 4]);
        qa[ks][3] = __half2float(qg[(long)(lq + 8) * LDQKV + ks * 8 + lr + 4]);
    }

    float m0 = -INFINITY, m1 = -INFINITY, l0 = 0.f, l1 = 0.f;
    float oacc[8][4];
    #pragma unroll
    for (int nt = 0; nt < 8; nt++)
        #pragma unroll
        for (int e = 0; e < 4; e++) oacc[nt][e] = 0.f;

    int lkr = tid >> 3;              // 0..63 row
    int lc8 = (tid & 7) << 3;        // 0..56 half-col

    for (int kt = 0; kt < 16; kt++) {
        int k0 = kt * 64;
        __syncthreads();
        {
            uint4 kv4 = *(const uint4*)(kg + (long)(k0 + lkr) * LDQKV + lc8);
            const __half2* hp = (const __half2*)&kv4;
            float2 f0 = __half22float2(hp[0]), f1 = __half22float2(hp[1]);
            float2 f2 = __half22float2(hp[2]), f3 = __half22float2(hp[3]);
            float4 lo = {f0.x, f0.y, f1.x, f1.y};
            float4 hi = {f2.x, f2.y, f3.x, f3.y};
            *(float4*)&Ks[lkr * KST + lc8]     = lo;
            *(float4*)&Ks[lkr * KST + lc8 + 4] = hi;

            uint4 vv4 = *(const uint4*)(vg + (long)(k0 + lkr) * LDQKV + lc8);
            const __half2* vp = (const __half2*)&vv4;
            float2 g0 = __half22float2(vp[0]), g1 = __half22float2(vp[1]);
            float2 g2 = __half22float2(vp[2]), g3 = __half22float2(vp[3]);
            float4 vlo = {g0.x, g0.y, g1.x, g1.y};
            float4 vhi = {g2.x, g2.y, g3.x, g3.y};
            int xo = (lkr & 3) << 3;
            *(float4*)&Vs[lkr * 64 + (lc8 ^ xo)]       = vlo;
            *(float4*)&Vs[lkr * 64 + ((lc8 + 4) ^ xo)] = vhi;
        }
        if (tid < 16) ((int4*)msk)[tid] = ((const int4*)(mrow + k0))[tid];
        __syncthreads();

        float sacc[8][4];
        #pragma unroll
        for (int nt = 0; nt < 8; nt++)
            #pragma unroll
            for (int e = 0; e < 4; e++) sacc[nt][e] = 0.f;

        #pragma unroll
        for (int nt = 0; nt < 8; nt++) {
            int rb = (nt * 8 + lq) * KST;
            #pragma unroll
            for (int ks = 0; ks < 8; ks++) {
                float b0 = Ks[rb + ks * 8 + lr];
                float b1 = Ks[rb + ks * 8 + lr + 4];
                mma_tf32(sacc[nt], qa[ks], b0, b1);
            }
        }

        float rmax0 = -INFINITY, rmax1 = -INFINITY;
        #pragma unroll
        for (int nt = 0; nt < 8; nt++) {
            int c = nt * 8 + lr * 2;
            int mk0 = msk[c], mk1 = msk[c + 1];
            float s0 = sacc[nt][0] * 0.125f; if (mk0 == 0) s0 = -1e9f;
            float s1 = sacc[nt][1] * 0.125f; if (mk1 == 0) s1 = -1e9f;
            float s2 = sacc[nt][2] * 0.125f; if (mk0 == 0) s2 = -1e9f;
            float s3 = sacc[nt][3] * 0.125f; if (mk1 == 0) s3 = -1e9f;
            sacc[nt][0] = s0; sacc[nt][1] = s1; sacc[nt][2] = s2; sacc[nt][3] = s3;
            rmax0 = fmaxf(rmax0, fmaxf(s0, s1));
            rmax1 = fmaxf(rmax1, fmaxf(s2, s3));
        }
        rmax0 = fmaxf(rmax0, __shfl_xor_sync(0xffffffffu, rmax0, 1));
        rmax0 = fmaxf(rmax0, __shfl_xor_sync(0xffffffffu, rmax0, 2));
        rmax1 = fmaxf(rmax1, __shfl_xor_sync(0xffffffffu, rmax1, 1));
        rmax1 = fmaxf(rmax1, __shfl_xor_sync(0xffffffffu, rmax1, 2));
        float mn0 = fmaxf(m0, rmax0), mn1 = fmaxf(m1, rmax1);
        float corr0 = __expf(m0 - mn0), corr1 = __expf(m1 - mn1);
        float ps0 = 0.f, ps1 = 0.f;
        #pragma unroll
        for (int nt = 0; nt < 8; nt++) {
            float p0 = __expf(sacc[nt][0] - mn0);
            float p1 = __expf(sacc[nt][1] - mn0);
            float p2 = __expf(sacc[nt][2] - mn1);
            float p3 = __expf(sacc[nt][3] - mn1);
            ps0 += p0 + p1; ps1 += p2 + p3;
            sacc[nt][0] = p0; sacc[nt][1] = p1; sacc[nt][2] = p2; sacc[nt][3] = p3;
        }
        ps0 += __shfl_xor_sync(0xffffffffu, ps0, 1);
        ps0 += __shfl_xor_sync(0xffffffffu, ps0, 2);
        ps1 += __shfl_xor_sync(0xffffffffu, ps1, 1);
        ps1 += __shfl_xor_sync(0xffffffffu, ps1, 2);
        l0 = l0 * corr0 + ps0; m0 = mn0;
        l1 = l1 * corr1 + ps1; m1 = mn1;
        #pragma unroll
        for (int nt = 0; nt < 8; nt++) {
            oacc[nt][0] *= corr0; oacc[nt][1] *= corr0;
            oacc[nt][2] *= corr1; oacc[nt][3] *= corr1;
        }

        int base = lane & ~3;
        int src0 = base | (lr >> 1);
        int src1 = src0 | 2;
        int sel = lr & 1;
        #pragma unroll
        for (int ks = 0; ks < 8; ks++) {
            float v0 = __shfl_sync(0xffffffffu, sacc[ks][0], src0);
            float v1 = __shfl_sync(0xffffffffu, sacc[ks][1], src0);
            float v2 = __shfl_sync(0xffffffffu, sacc[ks][2], src0);
            float v3 = __shfl_sync(0xffffffffu, sacc[ks][3], src0);
            float w0 = __shfl_sync(0xffffffffu, sacc[ks][0], src1);
            float w1 = __shfl_sync(0xffffffffu, sacc[ks][1], src1);
            float w2 = __shfl_sync(0xffffffffu, sacc[ks][2], src1);
            float w3 = __shfl_sync(0xffffffffu, sacc[ks][3], src1);
            float pa[4];
            pa[0] = sel ? v1 : v0;
            pa[1] = sel ? v3 : v2;
            pa[2] = sel ? w1 : w0;
            pa[3] = sel ? w3 : w2;
            int r0 = (ks * 8 + lr) * 64;
            int r1 = (ks * 8 + lr + 4) * 64;
            int xo = lr << 3;
            #pragma unroll
            for (int nt = 0; nt < 8; nt++) {
                int sw = (nt * 8 + lq) ^ xo;
                float b0 = Vs[r0 + sw];
                float b1 = Vs[r1 + sw];
                mma_tf32(oacc[nt], pa, b0, b1);
            }
        }
    }

    float inv0 = 1.f / l0, inv1 = 1.f / l1;
    long row0 = (long)(b * SS + q0 + w * 16 + lq) * DD + h * DKK;
    long row1 = row0 + 8 * DD;
    #pragma unroll
    for (int nt = 0; nt < 8; nt++) {
        int c = nt * 8 + lr * 2;
        *(__half2*)(ctx + row0 + c) = __floats2half2_rn(oacc[nt][0] * inv0, oacc[nt][1] * inv0);
        *(__half2*)(ctx + row1 + c) = __floats2half2_rn(oacc[nt][2] * inv1, oacc[nt][3] * inv1);
    }
}

extern "C" void kernel_launch(void* const* d_in, const int* in_sizes, int n_in,
                              void* d_out, int out_size)
{
    const float* x    = (const float*)d_in[0];
    const int*   mask = (const int*)  d_in[1];
    const float* wq = (const float*)d_in[2];  const float* bq = (const float*)d_in[3];
    const float* wk = (const float*)d_in[4];  const float* bk = (const float*)d_in[5];
    const float* wv = (const float*)d_in[6];  const float* bv = (const float*)d_in[7];
    const float* wo = (const float*)d_in[8];  const float* bo = (const float*)d_in[9];
    const float* w1 = (const float*)d_in[10]; const float* b1 = (const float*)d_in[11];
    const float* w2 = (const float*)d_in[12]; const float* b2 = (const float*)d_in[13];
    const float* a1 = (const float*)d_in[14]; const float* be1 = (const float*)d_in[15];
    const float* a2 = (const float*)d_in[16]; const float* be2 = (const float*)d_in[17];
    float* out = (float*)d_out;

    __half *xn, *qkv, *ctx, *xn2, *ffh, *wqkvt, *wot, *w1t, *w2t;
    float *x1, *bqkv;
    cudaGetSymbolAddress((void**)&xn,    g_xn);
    cudaGetSymbolAddress((void**)&qkv,   g_qkv);
    cudaGetSymbolAddress((void**)&ctx,   g_ctx);
    cudaGetSymbolAddress((void**)&x1,    g_x1);
    cudaGetSymbolAddress((void**)&xn2,   g_xn2);
    cudaGetSymbolAddress((void**)&ffh,   g_ffh);
    cudaGetSymbolAddress((void**)&wqkvt, g_wqkv);
    cudaGetSymbolAddress((void**)&wot,   g_wo);
    cudaGetSymbolAddress((void**)&w1t,   g_w1t);
    cudaGetSymbolAddress((void**)&w2t,   g_w2t);
    cudaGetSymbolAddress((void**)&bqkv,  g_bqkv);

    cudaFuncSetAttribute(mma_gemm16<true,false,false,true >, cudaFuncAttributeMaxDynamicSharedMemorySize, G_DYN);
    cudaFuncSetAttribute(mma_gemm16<true,false,true ,false>, cudaFuncAttributeMaxDynamicSharedMemorySize, G_DYN);
    cudaFuncSetAttribute(mma_gemm16<true,true ,false,true >, cudaFuncAttributeMaxDynamicSharedMemorySize, G_DYN);

    // weight prep: transpose to [N][K] + fp16 round (batched; bias concat fused)
    transpose4_f16<<<dim3(32, 32, 4), dim3(32, 8)>>>(
        wq, wk, wv, wo,
        wqkvt, wqkvt + DD * DD, wqkvt + 2 * DD * DD, wot,
        bq, bk, bv, bqkv);
    transpose_f16<<<dim3(128, 32), dim3(32, 8)>>>(w1, w1t, DD, DFFV);
    transpose_f16<<<dim3(32, 128), dim3(32, 8)>>>(w2, w2t, DFFV, DD);

    dim3 gQKV(LDQKV / 128, MR / 128);  // (24, 32)
    dim3 gD  (DD    / 128, MR / 128);  // (8, 32)
    dim3 gFF (DFFV  / 128, MR / 128);  // (32, 32)

    layernorm_kernel<<<MR, 256>>>(x, xn, a1, be1);
    mma_gemm16<true,false,false,true ><<<gQKV, 128, G_DYN>>>(xn, wqkvt, bqkv, nullptr, qkv, DD, LDQKV);
    attention_mma<<<dim3(SS / 256, BB * HH), 512>>>(qkv, mask, ctx);
    mma_gemm16<true,false,true ,false><<<gD, 128, G_DYN>>>(ctx, wot, bo, x, x1, DD, DD);
    layernorm_kernel<<<MR, 256>>>(x1, xn2, a2, be2);
    mma_gemm16<true,true ,false,true ><<<gFF, 128, G_DYN>>>(xn2, w1t, b1, nullptr, ffh, DD, DFFV);
    mma_gemm16<true,false,true ,false><<<gD, 128, G_DYN>>>(ffh, w2t, b2, x1, out, DFFV, DD);
}